// round 7
// baseline (speedup 1.0000x reference)
#include <cuda_runtime.h>
#include <math.h>

#define NB 16
#define NC 80
#define NLOC 17064
#define NBUCK 16384
#define REP 4
#define SEL_CAP 4096
#define TOPK 1000
#define MAXDET 100

// ---------------- static device scratch (no allocations) ----------------
__device__ int g_hist[NB * REP * NBUCK];
__device__ int g_selCount[NB];
__device__ int g_thr[NB];
__device__ float g_thrX[NB];
__device__ float g_cen[NB * NLOC];
__device__ unsigned long long g_sel[NB * SEL_CAP];   // (score_bits<<32)|(~idx)
__device__ float4 g_off4[NB][1024];                  // offset coords (x1,y1,x2,y2)
__device__ float  g_ar[NB][1024];                    // area on offset coords
__device__ float  g_pl[NB][6][1024];                 // px1,py1,px2,py2,sc,cf
__device__ unsigned g_mask[NB][32][1024];            // suppression rows, word-major

__global__ void dummy_kernel() {}

// ---------------- zero scratch ----------------
__global__ void zero_kernel() {
    int i = blockIdx.x * blockDim.x + threadIdx.x;
    int4* p = reinterpret_cast<int4*>(g_hist);
    if (i < NB * REP * NBUCK / 4) p[i] = make_int4(0, 0, 0, 0);
    if (i < NB) g_selCount[i] = 0;
}

// ---------------- centerness precompute ----------------
__global__ __launch_bounds__(256) void cen_kernel(
    const float* __restrict__ ct0, const float* __restrict__ ct1,
    const float* __restrict__ ct2, const float* __restrict__ ct3,
    const float* __restrict__ ct4)
{
    int b = blockIdx.y;
    int loc = blockIdx.x * 256 + threadIdx.x;
    if (loc >= NLOC) return;
    const float* p; int local;
    if      (loc < 12800) { p = ct0 + b * 12800; local = loc; }
    else if (loc < 16000) { p = ct1 + b * 3200;  local = loc - 12800; }
    else if (loc < 16800) { p = ct2 + b * 800;   local = loc - 16000; }
    else if (loc < 17008) { p = ct3 + b * 208;   local = loc - 16800; }
    else                  { p = ct4 + b * 56;    local = loc - 17008; }
    float x = p[local];
    g_cen[b * NLOC + loc] = __fdividef(1.0f, 1.0f + __expf(-x));
}

// ---------------- pass A: histogram ----------------
template<int HW, int LOCOFF>
__device__ __forceinline__ void hist_level(
    const float* __restrict__ lg, int b, int chunk, int rep)
{
    constexpr int CHW = NC * HW;
    const float* lp = lg + (size_t)b * CHW;
    const float* cenp = g_cen + b * NLOC + LOCOFF;
    int* hist = &g_hist[(b * REP + rep) * NBUCK];
    int e0 = chunk * 4096 + threadIdx.x * 4;
    float4 v[4];
    #pragma unroll
    for (int k = 0; k < 4; k++) {
        int e = e0 + k * 1024;
        v[k] = make_float4(-9e9f, -9e9f, -9e9f, -9e9f);
        if (e < CHW) v[k] = *reinterpret_cast<const float4*>(lp + e);
    }
    #pragma unroll
    for (int k = 0; k < 4; k++) {
        int e = e0 + k * 1024;
        int c  = e / HW;
        int hw = e - c * HW;
        float xs[4] = {v[k].x, v[k].y, v[k].z, v[k].w};
        #pragma unroll
        for (int i = 0; i < 4; i++) {
            float x = xs[i];
            if (x > -2.9445f) {                  // sigmoid(-2.9445) < 0.05 w/ margin
                float cls = __fdividef(1.0f, 1.0f + __expf(-x));
                if (cls > 0.05f) {
                    float comb = cls * cenp[hw + i];
                    atomicAdd(&hist[__float_as_uint(comb) >> 17], 1);
                }
            }
        }
    }
}

__global__ __launch_bounds__(256) void histA_kernel(
    const float* __restrict__ lg0, const float* __restrict__ lg1,
    const float* __restrict__ lg2, const float* __restrict__ lg3,
    const float* __restrict__ lg4)
{
    int bx = blockIdx.x, b = blockIdx.y, rep = bx & (REP - 1);
    if      (bx < 250) hist_level<12800,     0>(lg0, b, bx,       rep);
    else if (bx < 313) hist_level< 3200, 12800>(lg1, b, bx - 250, rep);
    else if (bx < 329) hist_level<  800, 16000>(lg2, b, bx - 313, rep);
    else if (bx < 334) hist_level<  208, 16800>(lg3, b, bx - 329, rep);
    else               hist_level<   56, 17008>(lg4, b, bx - 334, rep);
}

// ---------------- pass 2: threshold from histogram ----------------
__global__ void pass2_kernel() {
    int b = blockIdx.x;
    __shared__ int csum[256];
    __shared__ int sval[64];
    __shared__ int s_j, s_cumbefore;
    int t = threadIdx.x;
    const int* hb = &g_hist[b * REP * NBUCK];

    int s = 0;
    for (int r = t * 64; r < t * 64 + 64; r++) {
        int bucket = NBUCK - 1 - r;
        int v = 0;
        #pragma unroll
        for (int rp = 0; rp < REP; rp++) v += hb[rp * NBUCK + bucket];
        s += v;
    }
    csum[t] = s;
    __syncthreads();
    if (t == 0) {
        int cum = 0, j = 255;
        for (int q = 0; q < 256; q++) {
            if (cum + csum[q] >= TOPK) { j = q; break; }
            cum += csum[q];
        }
        s_j = j; s_cumbefore = cum;
    }
    __syncthreads();
    int j = s_j;
    if (t < 64) {
        int bucket = NBUCK - 1 - (j * 64 + t);
        int v = 0;
        #pragma unroll
        for (int rp = 0; rp < REP; rp++) v += hb[rp * NBUCK + bucket];
        sval[t] = v;
    }
    __syncthreads();
    if (t == 0) {
        int cum = s_cumbefore, thr = 0;
        for (int q = 0; q < 64; q++) {
            cum += sval[q];
            if (cum >= TOPK) { thr = NBUCK - 1 - (j * 64 + q); break; }
        }
        g_thr[b] = thr;
        float tX = -2.9445f;
        if (thr > 0) {
            float cm = __uint_as_float((unsigned)thr << 17);  // bucket lower edge
            if (cm > 0.0f && cm < 1.0f)
                tX = fmaxf(tX, logf(cm / (1.0f - cm)) - 1e-3f); // cls >= comb >= cm
        }
        g_thrX[b] = tX;
    }
}

// ---------------- pass B: selective re-read, direct candidate write ----------------
template<int HW, int LOCOFF>
__device__ __forceinline__ void sel_level(
    const float* __restrict__ lg, int b, int chunk, unsigned thr, float thrX)
{
    constexpr int CHW = NC * HW;
    const float* lp = lg + (size_t)b * CHW;
    const float* cenp = g_cen + b * NLOC + LOCOFF;
    int e0 = chunk * 4096 + threadIdx.x * 4;
    float4 v[4];
    #pragma unroll
    for (int k = 0; k < 4; k++) {
        int e = e0 + k * 1024;
        v[k] = make_float4(-9e9f, -9e9f, -9e9f, -9e9f);
        if (e < CHW) v[k] = *reinterpret_cast<const float4*>(lp + e);
    }
    #pragma unroll
    for (int k = 0; k < 4; k++) {
        int e = e0 + k * 1024;
        int c  = e / HW;
        int hw = e - c * HW;
        float xs[4] = {v[k].x, v[k].y, v[k].z, v[k].w};
        #pragma unroll
        for (int i = 0; i < 4; i++) {
            float x = xs[i];
            if (x > thrX) {
                float cls = __fdividef(1.0f, 1.0f + __expf(-x));
                if (cls > 0.05f) {
                    float comb = cls * cenp[hw + i];
                    unsigned bits = __float_as_uint(comb);
                    if ((bits >> 17) >= thr) {
                        unsigned idx = (unsigned)((LOCOFF + hw + i) * NC + c);
                        int p = atomicAdd(&g_selCount[b], 1);
                        if (p < SEL_CAP)
                            g_sel[b * SEL_CAP + p] =
                                ((unsigned long long)bits << 32) |
                                (unsigned long long)(0xFFFFFFFFu - idx);
                    }
                }
            }
        }
    }
}

__global__ __launch_bounds__(256) void selB_kernel(
    const float* __restrict__ lg0, const float* __restrict__ lg1,
    const float* __restrict__ lg2, const float* __restrict__ lg3,
    const float* __restrict__ lg4)
{
    int bx = blockIdx.x, b = blockIdx.y;
    unsigned thr = (unsigned)g_thr[b];
    float thrX = g_thrX[b];
    if      (bx < 250) sel_level<12800,     0>(lg0, b, bx,       thr, thrX);
    else if (bx < 313) sel_level< 3200, 12800>(lg1, b, bx - 250, thr, thrX);
    else if (bx < 329) sel_level<  800, 16000>(lg2, b, bx - 313, thr, thrX);
    else if (bx < 334) sel_level<  208, 16800>(lg3, b, bx - 329, thr, thrX);
    else               sel_level<   56, 17008>(lg4, b, bx - 334, thr, thrX);
}

// ---------------- sort + decode ----------------
__device__ __forceinline__ unsigned long long u64max(unsigned long long a, unsigned long long b) { return a > b ? a : b; }
__device__ __forceinline__ unsigned long long u64min(unsigned long long a, unsigned long long b) { return a < b ? a : b; }

__global__ __launch_bounds__(1024) void sortdec_kernel(
    const float* __restrict__ bb0, const float* __restrict__ bb1,
    const float* __restrict__ bb2, const float* __restrict__ bb3,
    const float* __restrict__ bb4, const float* __restrict__ iminfo)
{
    int b = blockIdx.x;
    int t = threadIdx.x;
    __shared__ unsigned long long key[SEL_CAP];

    int cnt = min(g_selCount[b], SEL_CAP);
    int n2 = 1024;
    while (n2 < cnt) n2 <<= 1;

    for (int i = t; i < n2; i += 1024)
        key[i] = (i < cnt) ? g_sel[b * SEL_CAP + i] : 0ULL;
    __syncthreads();

    // bitonic sort descending; key = (score_bits<<32)|(~idx)
    for (int k = 2; k <= n2; k <<= 1) {
        for (int j = k >> 1; j >= 32; j >>= 1) {
            for (int i = t; i < n2; i += 1024) {
                int ixj = i ^ j;
                if (ixj > i) {
                    bool desc = (i & k) == 0;
                    unsigned long long a = key[i], c = key[ixj];
                    if (desc ? (a < c) : (a > c)) { key[i] = c; key[ixj] = a; }
                }
            }
            __syncthreads();
        }
        // fused j<=16 stages via warp shuffle (partners within 32-elem chunks)
        int j0 = min(k >> 1, 16);
        for (int c0 = (t >> 5); c0 < (n2 >> 5); c0 += 32) {
            int idx = c0 * 32 + (t & 31);
            unsigned long long v = key[idx];
            bool desc = (idx & k) == 0;
            for (int j = j0; j >= 1; j >>= 1) {
                unsigned long long p = __shfl_xor_sync(0xFFFFFFFFu, v, j);
                bool keepmax = (((idx & j) == 0) == desc);
                v = keepmax ? u64max(v, p) : u64min(v, p);
            }
            key[idx] = v;
        }
        __syncthreads();
    }

    if (t < TOPK) {
        unsigned long long kk = key[t];
        unsigned bits = (unsigned)(kk >> 32);
        float x1 = 0.f, y1 = 0.f, x2 = 0.f, y2 = 0.f, sc = 0.f, cf = 0.f;
        if (bits != 0u) {
            unsigned idx = 0xFFFFFFFFu - (unsigned)(kk & 0xFFFFFFFFu);
            int loc = (int)(idx / NC);
            int c   = (int)(idx % NC);
            const int offs[5]    = {0, 12800, 16000, 16800, 17008};
            const int Ws[5]      = {128, 64, 32, 16, 8};
            const int HWs[5]     = {12800, 3200, 800, 208, 56};
            const int strides[5] = {8, 16, 32, 64, 128};
            const float* bbs[5]  = {bb0, bb1, bb2, bb3, bb4};
            int lvl = 4;
            if      (loc < 12800) lvl = 0;
            else if (loc < 16000) lvl = 1;
            else if (loc < 16800) lvl = 2;
            else if (loc < 17008) lvl = 3;
            int local = loc - offs[lvl];
            int W = Ws[lvl], HW = HWs[lvl], st = strides[lvl];
            int hh = local / W;
            int ww = local - hh * W;
            float cx = (float)(ww * st + (st >> 1));
            float cy = (float)(hh * st + (st >> 1));
            const float* bp = bbs[lvl] + (size_t)b * 4 * HW + local;
            float r0 = bp[0], r1 = bp[HW], r2 = bp[2 * HW], r3 = bp[3 * HW];
            float ih = iminfo[b * 2 + 0];
            float iw = iminfo[b * 2 + 1];
            x1 = fminf(fmaxf(cx - r0, 0.0f), iw - 1.0f);
            y1 = fminf(fmaxf(cy - r1, 0.0f), ih - 1.0f);
            x2 = fminf(fmaxf(cx + r2, 0.0f), iw - 1.0f);
            y2 = fminf(fmaxf(cy + r3, 0.0f), ih - 1.0f);
            sc = sqrtf(__uint_as_float(bits) + 1e-12f);
            cf = (float)c;
        }
        float off = cf * 10000.0f;
        float ox1 = x1 + off, oy1 = y1 + off, ox2 = x2 + off, oy2 = y2 + off;
        g_off4[b][t] = make_float4(ox1, oy1, ox2, oy2);
        g_ar[b][t]   = fmaxf(ox2 - ox1, 0.0f) * fmaxf(oy2 - oy1, 0.0f);
        g_pl[b][0][t] = x1; g_pl[b][1][t] = y1; g_pl[b][2][t] = x2;
        g_pl[b][3][t] = y2; g_pl[b][4][t] = sc; g_pl[b][5][t] = cf;
    }
}

// ---------------- suppression-mask matrix ----------------
__global__ __launch_bounds__(128) void mask_kernel() {
    int b = blockIdx.x;
    __shared__ float4 sb[TOPK];
    __shared__ float sar[TOPK];
    for (int i = threadIdx.x; i < TOPK; i += 128) {
        sb[i] = g_off4[b][i];
        sar[i] = g_ar[b][i];
    }
    __syncthreads();
    int i = blockIdx.y * 125 + threadIdx.x;
    if (threadIdx.x >= 125 || i >= TOPK) return;
    float4 bi = sb[i];
    float ai = sar[i];
    unsigned cur = 0;
    for (int j = 0; j < TOPK; j++) {
        float4 bj = sb[j];
        float xx1 = fmaxf(bi.x, bj.x), yy1 = fmaxf(bi.y, bj.y);
        float xx2 = fminf(bi.z, bj.z), yy2 = fminf(bi.w, bj.w);
        float inter = fmaxf(xx2 - xx1, 0.0f) * fmaxf(yy2 - yy1, 0.0f);
        float iou = inter / (ai + sar[j] - inter + 1e-9f);
        bool s = (iou >= 0.6f) || (j == i);
        cur |= ((unsigned)s) << (j & 31);
        if ((j & 31) == 31) { g_mask[b][j >> 5][i] = cur; cur = 0; }
    }
    g_mask[b][31][i] = cur;   // j = 992..999 remainder (high bits 0)
}

// ---------------- serial greedy walk over bitmaps ----------------
__global__ __launch_bounds__(1024) void walk_kernel(float* __restrict__ out) {
    extern __shared__ unsigned sm[];
    unsigned* msk = sm;                       // [32][1033] padded
    float* scs = (float*)(sm + 32 * 1033);
    float* px1 = scs + 1024; float* py1 = px1 + 1024; float* px2 = py1 + 1024;
    float* py2 = px2 + 1024; float* pcf = py2 + 1024;
    int b = blockIdx.x, t = threadIdx.x;

    if (t < MAXDET * 6) out[(size_t)b * MAXDET * 6 + t] = 0.0f;

    const unsigned* gm = &g_mask[b][0][0];
    for (int u = t; u < 32 * 1024; u += 1024) {
        int w = u >> 10, i = u & 1023;
        msk[w * 1033 + i] = gm[u];
    }
    bool real = (t < TOPK);
    scs[t] = real ? g_pl[b][4][t] : 0.0f;
    px1[t] = real ? g_pl[b][0][t] : 0.0f;
    py1[t] = real ? g_pl[b][1][t] : 0.0f;
    px2[t] = real ? g_pl[b][2][t] : 0.0f;
    py2[t] = real ? g_pl[b][3][t] : 0.0f;
    pcf[t] = real ? g_pl[b][5][t] : 0.0f;
    __syncthreads();

    if (t < 32) {
        int lane = t;
        unsigned removed = (lane == 31) ? 0xFFFFFF00u : 0u;  // mark i >= 1000
        for (int outk = 0; outk < MAXDET; outk++) {
            unsigned avail = ~removed;
            int first = avail ? (lane * 32 + __ffs(avail) - 1) : (1 << 30);
            #pragma unroll
            for (int d = 16; d > 0; d >>= 1)
                first = min(first, __shfl_xor_sync(0xFFFFFFFFu, first, d));
            if (first >= TOPK) break;
            float s = scs[first];
            if (s <= 0.0f) break;
            if (lane == 0) {
                float* o = out + (size_t)(b * MAXDET + outk) * 6;
                o[0] = px1[first]; o[1] = py1[first]; o[2] = px2[first];
                o[3] = py2[first]; o[4] = s;          o[5] = pcf[first];
            }
            removed |= msk[lane * 1033 + first];
        }
    }
}

// ---------------- launch ----------------
extern "C" void kernel_launch(void* const* d_in, const int* in_sizes, int n_in,
                              void* d_out, int out_size) {
    (void)in_sizes; (void)n_in; (void)out_size;
    const float* lg[5]; const float* bb[5]; const float* ct[5];
    for (int l = 0; l < 5; l++) {
        lg[l] = (const float*)d_in[3 * l + 0];
        bb[l] = (const float*)d_in[3 * l + 1];
        ct[l] = (const float*)d_in[3 * l + 2];
    }
    const float* iminfo = (const float*)d_in[15];
    float* out = (float*)d_out;

    const int WALK_SMEM = (32 * 1033) * 4 + 6 * 1024 * 4;   // 156800 B
    static bool attr_done = false;
    if (!attr_done) {
        cudaFuncSetAttribute(walk_kernel, cudaFuncAttributeMaxDynamicSharedMemorySize, WALK_SMEM);
        attr_done = true;
    }

    zero_kernel<<<(NB * REP * NBUCK / 4 + 255) / 256, 256>>>();
    cen_kernel<<<dim3((NLOC + 255) / 256, NB), 256>>>(ct[0], ct[1], ct[2], ct[3], ct[4]);
    dummy_kernel<<<1, 1>>>();   // make histA launch #4 for ncu capture
    histA_kernel<<<dim3(336, NB), 256>>>(lg[0], lg[1], lg[2], lg[3], lg[4]);
    pass2_kernel<<<NB, 256>>>();
    selB_kernel<<<dim3(336, NB), 256>>>(lg[0], lg[1], lg[2], lg[3], lg[4]);
    sortdec_kernel<<<NB, 1024>>>(bb[0], bb[1], bb[2], bb[3], bb[4], iminfo);
    mask_kernel<<<dim3(NB, 8), 128>>>();
    walk_kernel<<<NB, 1024, WALK_SMEM>>>(out);
}